// round 6
// baseline (speedup 1.0000x reference)
#include <cuda_runtime.h>
#include <cstdint>

#define C_    80
#define H_    32
#define W_    88
#define HW_   (H_ * W_)          // 2816
#define NXg   128
#define NYg   128
#define NZg   16
#define NPTS  (NXg * NYg * NZg)  // 262144 points per batch
#define TPB   256
#define PPT   4                  // points per thread (share ix,iy; STG.128 stores)
#define NCH4  (C_ / 4)           // 20 channel chunks

// (B, H*W, C) channel-last copy of the feature map. 2*2816*80 floats = 1.8 MB.
__device__ float g_imgT[2 * HW_ * C_];

// ---------------------------------------------------------------------------
// Pass 1: (B, C, HW) -> (B, HW, C) tiled transpose
// ---------------------------------------------------------------------------
__global__ void fvt_transpose(const float* __restrict__ img)
{
    __shared__ float tile[32][33];
    const int b   = blockIdx.z;
    const int hw0 = blockIdx.x * 32;
    const int c0  = blockIdx.y * 32;
    const int tx  = threadIdx.x;      // 0..31
    const int ty  = threadIdx.y;      // 0..7

    #pragma unroll
    for (int i = 0; i < 4; i++) {
        const int c  = c0 + ty + i * 8;
        const int hw = hw0 + tx;
        if (c < C_ && hw < HW_)
            tile[ty + i * 8][tx] = img[((size_t)b * C_ + c) * HW_ + hw];
    }
    __syncthreads();
    #pragma unroll
    for (int i = 0; i < 4; i++) {
        const int hw = hw0 + ty + i * 8;
        const int c  = c0 + tx;
        if (hw < HW_ && c < C_)
            g_imgT[((size_t)b * HW_ + hw) * C_ + c] = tile[tx][ty + i * 8];
    }
}

// ---------------------------------------------------------------------------
// Pass 2: project + bilinear gather (channel-vectorized) + STG.128 stores
// ---------------------------------------------------------------------------
__global__ __launch_bounds__(TPB, 3) void fvt_kernel(
    const float* __restrict__ intrin,  // (B, 1, 4, 4)
    const float* __restrict__ extrin,  // (B, 1, 4, 4)
    const float* __restrict__ bda,     // (B, 4, 4)
    float* __restrict__ out)           // (B, C, NX, NY, NZ)
{
    __shared__ float s_bda[16];
    __shared__ float s_proj[12];

    const int b = blockIdx.y;

    if (threadIdx.x < 16) s_bda[threadIdx.x] = bda[b * 16 + threadIdx.x];
    if (threadIdx.x < 12) {
        // proj[i][j] = sum_k (intrin[i][k] * scale_i) * extrin[k][j]
        const int i = threadIdx.x >> 2;
        const int j = threadIdx.x & 3;
        const float sc = (i < 2) ? 0.125f : 1.0f;
        const float* IN = intrin + b * 16;
        const float* EX = extrin + b * 16;
        float acc = 0.0f;
        #pragma unroll
        for (int k = 0; k < 3; k++)
            acc += (IN[i * 4 + k] * sc) * EX[k * 4 + j];
        s_proj[threadIdx.x] = acc;
    }
    __syncthreads();

    const int n0 = (blockIdx.x * TPB + threadIdx.x) * PPT;
    // all PPT points share (ix, iy): iz = n & 15 and PPT | 16
    const int t  = n0 >> 4;
    const int iy = t & (NYg - 1);
    const int ix = t >> 7;
    const int iz0 = n0 & (NZg - 1);

    const float px = __fadd_rn(__fmul_rn((float)ix, 0.8f), -51.2f);
    const float py = __fadd_rn(__fmul_rn((float)iy, 0.8f), -51.2f);

    int   off[PPT][4];     // byte-ish offsets (float index) of 4 corners
    float w  [PPT][4];
    bool  pany[PPT];
    bool  any = false;

    #pragma unroll
    for (int p = 0; p < PPT; p++) {
        const float pz = __fadd_rn(__fmul_rn((float)(iz0 + p), 0.5f), -5.0f);

        // q = bda @ [px,py,pz,1]
        const float q0 = s_bda[ 0]*px + s_bda[ 1]*py + s_bda[ 2]*pz + s_bda[ 3];
        const float q1 = s_bda[ 4]*px + s_bda[ 5]*py + s_bda[ 6]*pz + s_bda[ 7];
        const float q2 = s_bda[ 8]*px + s_bda[ 9]*py + s_bda[10]*pz + s_bda[11];
        const float q3 = s_bda[12]*px + s_bda[13]*py + s_bda[14]*pz + s_bda[15];

        // pix = proj(3x4) @ q
        const float p0 = s_proj[0]*q0 + s_proj[1]*q1 + s_proj[ 2]*q2 + s_proj[ 3]*q3;
        const float p1 = s_proj[4]*q0 + s_proj[5]*q1 + s_proj[ 6]*q2 + s_proj[ 7]*q3;
        const float p2 = s_proj[8]*q0 + s_proj[9]*q1 + s_proj[10]*q2 + s_proj[11]*q3;

        const float u = __fdiv_rn(p0, p2);
        const float v = __fdiv_rn(p1, p2);

        const float un = __fadd_rn(__fmul_rn(__fdiv_rn(u, 88.0f), 2.0f), -1.0f);
        const float vn = __fadd_rn(__fmul_rn(__fdiv_rn(v, 32.0f), 2.0f), -1.0f);
        float x = __fmul_rn(__fmul_rn(__fadd_rn(un, 1.0f), 0.5f), 87.0f);
        float y = __fmul_rn(__fmul_rn(__fadd_rn(vn, 1.0f), 0.5f), 31.0f);

        // finite check via exponent bits (robust under any fast-math setting)
        const unsigned exb = __float_as_uint(x) & 0x7f800000u;
        const unsigned eyb = __float_as_uint(y) & 0x7f800000u;
        if (exb == 0x7f800000u || eyb == 0x7f800000u) { x = -10.0f; y = -10.0f; }

        const float x0f = floorf(x), y0f = floorf(y);
        const float x1f = x0f + 1.0f, y1f = y0f + 1.0f;
        const float wx1 = x - x0f, wx0 = 1.0f - wx1;
        const float wy1 = y - y0f, wy0 = 1.0f - wy1;

        const bool vx0 = (x0f >= 0.0f) && (x0f < 88.0f);
        const bool vx1 = (x1f >= 0.0f) && (x1f < 88.0f);
        const bool vy0 = (y0f >= 0.0f) && (y0f < 32.0f);
        const bool vy1 = (y1f >= 0.0f) && (y1f < 32.0f);

        const int ix0 = (int)fminf(fmaxf(x0f, 0.0f), 87.0f);
        const int ix1 = (int)fminf(fmaxf(x1f, 0.0f), 87.0f);
        const int iy0 = (int)fminf(fmaxf(y0f, 0.0f), 31.0f);
        const int iy1 = (int)fminf(fmaxf(y1f, 0.0f), 31.0f);

        off[p][0] = (iy0 * W_ + ix0) * C_;
        off[p][1] = (iy0 * W_ + ix1) * C_;
        off[p][2] = (iy1 * W_ + ix0) * C_;
        off[p][3] = (iy1 * W_ + ix1) * C_;

        w[p][0] = (vx0 && vy0) ? wx0 * wy0 : 0.0f;
        w[p][1] = (vx1 && vy0) ? wx1 * wy0 : 0.0f;
        w[p][2] = (vx0 && vy1) ? wx0 * wy1 : 0.0f;
        w[p][3] = (vx1 && vy1) ? wx1 * wy1 : 0.0f;

        pany[p] = (vx0 || vx1) && (vy0 || vy1);
        any = any || pany[p];
    }

    float4* ob = (float4*)(out + (size_t)b * C_ * NPTS + n0);
    const int stride4 = NPTS / 4;      // float4 stride between channels

    if (!any) {
        const float4 z = make_float4(0.0f, 0.0f, 0.0f, 0.0f);
        #pragma unroll 8
        for (int c = 0; c < C_; c++)
            __stcs(ob + c * stride4, z);
        return;
    }

    const float* rowbase = g_imgT + (size_t)b * HW_ * C_;

    #pragma unroll 2
    for (int ch = 0; ch < NCH4; ch++) {
        float r[PPT][4];   // r[p] = 4 channels of point p
        #pragma unroll
        for (int p = 0; p < PPT; p++) {
            if (pany[p]) {
                const float4 a = __ldg((const float4*)(rowbase + off[p][0]) + ch);
                const float4 bq= __ldg((const float4*)(rowbase + off[p][1]) + ch);
                const float4 cq= __ldg((const float4*)(rowbase + off[p][2]) + ch);
                const float4 dq= __ldg((const float4*)(rowbase + off[p][3]) + ch);
                r[p][0] = w[p][0]*a.x + w[p][1]*bq.x + w[p][2]*cq.x + w[p][3]*dq.x;
                r[p][1] = w[p][0]*a.y + w[p][1]*bq.y + w[p][2]*cq.y + w[p][3]*dq.y;
                r[p][2] = w[p][0]*a.z + w[p][1]*bq.z + w[p][2]*cq.z + w[p][3]*dq.z;
                r[p][3] = w[p][0]*a.w + w[p][1]*bq.w + w[p][2]*cq.w + w[p][3]*dq.w;
            } else {
                r[p][0] = r[p][1] = r[p][2] = r[p][3] = 0.0f;
            }
        }
        // transpose in registers: store float4 along the point axis per channel
        #pragma unroll
        for (int cc = 0; cc < 4; cc++) {
            float4 s;
            s.x = r[0][cc]; s.y = r[1][cc]; s.z = r[2][cc]; s.w = r[3][cc];
            __stcs(ob + (ch * 4 + cc) * stride4, s);
        }
    }
}

extern "C" void kernel_launch(void* const* d_in, const int* in_sizes, int n_in,
                              void* d_out, int out_size)
{
    (void)in_sizes; (void)n_in; (void)out_size;
    const float* img    = (const float*)d_in[0];
    const float* intrin = (const float*)d_in[1];
    const float* extrin = (const float*)d_in[2];
    const float* bda    = (const float*)d_in[3];
    float* out          = (float*)d_out;

    dim3 tgrid((HW_ + 31) / 32, (C_ + 31) / 32, 2);
    fvt_transpose<<<tgrid, dim3(32, 8)>>>(img);

    dim3 grid(NPTS / (TPB * PPT), 2);   // 256 blocks/batch, B=2
    fvt_kernel<<<grid, TPB>>>(intrin, extrin, bda, out);
}

// round 9
// speedup vs baseline: 1.1998x; 1.1998x over previous
#include <cuda_runtime.h>
#include <cstdint>

#define C_    80
#define H_    32
#define W_    88
#define HW_   (H_ * W_)          // 2816
#define NXg   128
#define NYg   128
#define NZg   16
#define NPTS  (NXg * NYg * NZg)  // 262144 points per batch
#define TPB   256
#define NCH4  (C_ / 4)           // 20 channel chunks

// (B, H*W, C) channel-last copy of the feature map. 2*2816*80 floats = 1.8 MB.
__device__ float g_imgT[2 * HW_ * C_];

// ---------------------------------------------------------------------------
// Pass 1: (B, C, HW) -> (B, HW, C) tiled transpose  (stays resident in L2)
// ---------------------------------------------------------------------------
__global__ void fvt_transpose(const float* __restrict__ img)
{
    __shared__ float tile[32][33];
    const int b   = blockIdx.z;
    const int hw0 = blockIdx.x * 32;
    const int c0  = blockIdx.y * 32;
    const int tx  = threadIdx.x;      // 0..31
    const int ty  = threadIdx.y;      // 0..7

    #pragma unroll
    for (int i = 0; i < 4; i++) {
        const int c  = c0 + ty + i * 8;
        const int hw = hw0 + tx;
        if (c < C_ && hw < HW_)
            tile[ty + i * 8][tx] = img[((size_t)b * C_ + c) * HW_ + hw];
    }
    __syncthreads();
    #pragma unroll
    for (int i = 0; i < 4; i++) {
        const int hw = hw0 + ty + i * 8;
        const int c  = c0 + tx;
        if (hw < HW_ && c < C_)
            g_imgT[((size_t)b * HW_ + hw) * C_ + c] = tile[tx][ty + i * 8];
    }
}

// ---------------------------------------------------------------------------
// Pass 2: thread-per-point, channel-vectorized gather, streamed stores.
// Occupancy is the lever: <=51 regs, 5 blocks/SM (62.5% theoretical occ).
// ---------------------------------------------------------------------------
__global__ __launch_bounds__(TPB, 5) void fvt_kernel(
    const float* __restrict__ intrin,  // (B, 1, 4, 4)
    const float* __restrict__ extrin,  // (B, 1, 4, 4)
    const float* __restrict__ bda,     // (B, 4, 4)
    float* __restrict__ out)           // (B, C, NX, NY, NZ)
{
    __shared__ float s_bda[16];
    __shared__ float s_proj[12];

    const int b = blockIdx.y;

    if (threadIdx.x < 16) s_bda[threadIdx.x] = bda[b * 16 + threadIdx.x];
    if (threadIdx.x < 12) {
        // proj[i][j] = sum_k (intrin[i][k] * scale_i) * extrin[k][j]
        const int i = threadIdx.x >> 2;
        const int j = threadIdx.x & 3;
        const float sc = (i < 2) ? 0.125f : 1.0f;
        const float* IN = intrin + b * 16;
        const float* EX = extrin + b * 16;
        float acc = 0.0f;
        #pragma unroll
        for (int k = 0; k < 3; k++)
            acc += (IN[i * 4 + k] * sc) * EX[k * 4 + j];
        s_proj[threadIdx.x] = acc;
    }
    __syncthreads();

    const int n  = blockIdx.x * TPB + threadIdx.x;
    const int iz = n & (NZg - 1);
    const int t  = n >> 4;
    const int iy = t & (NYg - 1);
    const int ix = t >> 7;

    // match jnp: bound[0] + arange*step  (mul then add, no FMA contraction)
    const float px = __fadd_rn(__fmul_rn((float)ix, 0.8f), -51.2f);
    const float py = __fadd_rn(__fmul_rn((float)iy, 0.8f), -51.2f);
    const float pz = __fadd_rn(__fmul_rn((float)iz, 0.5f), -5.0f);

    // q = bda @ [px,py,pz,1]
    const float q0 = s_bda[ 0]*px + s_bda[ 1]*py + s_bda[ 2]*pz + s_bda[ 3];
    const float q1 = s_bda[ 4]*px + s_bda[ 5]*py + s_bda[ 6]*pz + s_bda[ 7];
    const float q2 = s_bda[ 8]*px + s_bda[ 9]*py + s_bda[10]*pz + s_bda[11];
    const float q3 = s_bda[12]*px + s_bda[13]*py + s_bda[14]*pz + s_bda[15];

    // pix = proj(3x4) @ q
    const float p0 = s_proj[0]*q0 + s_proj[1]*q1 + s_proj[ 2]*q2 + s_proj[ 3]*q3;
    const float p1 = s_proj[4]*q0 + s_proj[5]*q1 + s_proj[ 6]*q2 + s_proj[ 7]*q3;
    const float p2 = s_proj[8]*q0 + s_proj[9]*q1 + s_proj[10]*q2 + s_proj[11]*q3;

    const float u = __fdiv_rn(p0, p2);
    const float v = __fdiv_rn(p1, p2);

    // un = u/W*2-1 ; x = (un+1)*0.5*(W-1)   (replicate reference op order)
    const float un = __fadd_rn(__fmul_rn(__fdiv_rn(u, 88.0f), 2.0f), -1.0f);
    const float vn = __fadd_rn(__fmul_rn(__fdiv_rn(v, 32.0f), 2.0f), -1.0f);
    float x = __fmul_rn(__fmul_rn(__fadd_rn(un, 1.0f), 0.5f), 87.0f);
    float y = __fmul_rn(__fmul_rn(__fadd_rn(vn, 1.0f), 0.5f), 31.0f);

    // finite check via exponent bits (robust under any fast-math setting)
    const unsigned exb = __float_as_uint(x) & 0x7f800000u;
    const unsigned eyb = __float_as_uint(y) & 0x7f800000u;
    if (exb == 0x7f800000u || eyb == 0x7f800000u) { x = -10.0f; y = -10.0f; }

    const float x0f = floorf(x), y0f = floorf(y);
    const float x1f = x0f + 1.0f, y1f = y0f + 1.0f;
    const float wx1 = x - x0f, wx0 = 1.0f - wx1;
    const float wy1 = y - y0f, wy0 = 1.0f - wy1;

    const bool vx0 = (x0f >= 0.0f) && (x0f < 88.0f);
    const bool vx1 = (x1f >= 0.0f) && (x1f < 88.0f);
    const bool vy0 = (y0f >= 0.0f) && (y0f < 32.0f);
    const bool vy1 = (y1f >= 0.0f) && (y1f < 32.0f);

    const int ix0 = (int)fminf(fmaxf(x0f, 0.0f), 87.0f);
    const int ix1 = (int)fminf(fmaxf(x1f, 0.0f), 87.0f);
    const int iy0 = (int)fminf(fmaxf(y0f, 0.0f), 31.0f);
    const int iy1 = (int)fminf(fmaxf(y1f, 0.0f), 31.0f);

    const float w00 = (vx0 && vy0) ? wx0 * wy0 : 0.0f;
    const float w10 = (vx1 && vy0) ? wx1 * wy0 : 0.0f;
    const float w01 = (vx0 && vy1) ? wx0 * wy1 : 0.0f;
    const float w11 = (vx1 && vy1) ? wx1 * wy1 : 0.0f;

    const bool any = (vx0 || vx1) && (vy0 || vy1);

    float* ob = out + (size_t)b * C_ * NPTS + n;

    if (!any) {
        #pragma unroll
        for (int c = 0; c < C_; c++)
            __stcs(ob + (size_t)c * NPTS, 0.0f);
        return;
    }

    const float* rowbase = g_imgT + (size_t)b * HW_ * C_;
    const float4* pc00 = (const float4*)(rowbase + (size_t)(iy0 * W_ + ix0) * C_);
    const float4* pc10 = (const float4*)(rowbase + (size_t)(iy0 * W_ + ix1) * C_);
    const float4* pc01 = (const float4*)(rowbase + (size_t)(iy1 * W_ + ix0) * C_);
    const float4* pc11 = (const float4*)(rowbase + (size_t)(iy1 * W_ + ix1) * C_);

    for (int ch = 0; ch < NCH4; ch++) {
        // front-batch the 4 corner loads (MLP=4) before any math
        const float4 a  = __ldg(pc00 + ch);
        const float4 bq = __ldg(pc10 + ch);
        const float4 cq = __ldg(pc01 + ch);
        const float4 dq = __ldg(pc11 + ch);
        float4 r;
        r.x = w00*a.x + w10*bq.x + w01*cq.x + w11*dq.x;
        r.y = w00*a.y + w10*bq.y + w01*cq.y + w11*dq.y;
        r.z = w00*a.z + w10*bq.z + w01*cq.z + w11*dq.z;
        r.w = w00*a.w + w10*bq.w + w01*cq.w + w11*dq.w;
        float* o = ob + (size_t)(ch * 4) * NPTS;
        __stcs(o,            r.x);
        __stcs(o +     NPTS, r.y);
        __stcs(o + 2 * NPTS, r.z);
        __stcs(o + 3 * NPTS, r.w);
    }
}

extern "C" void kernel_launch(void* const* d_in, const int* in_sizes, int n_in,
                              void* d_out, int out_size)
{
    (void)in_sizes; (void)n_in; (void)out_size;
    const float* img    = (const float*)d_in[0];
    const float* intrin = (const float*)d_in[1];
    const float* extrin = (const float*)d_in[2];
    const float* bda    = (const float*)d_in[3];
    float* out          = (float*)d_out;

    dim3 tgrid((HW_ + 31) / 32, (C_ + 31) / 32, 2);
    fvt_transpose<<<tgrid, dim3(32, 8)>>>(img);

    dim3 grid(NPTS / TPB, 2);   // 1024 blocks/batch, B=2
    fvt_kernel<<<grid, TPB>>>(intrin, extrin, bda, out);
}

// round 10
// speedup vs baseline: 1.2619x; 1.0517x over previous
#include <cuda_runtime.h>
#include <cuda_fp16.h>
#include <cstdint>

#define C_    80
#define H_    32
#define W_    88
#define HW_   (H_ * W_)          // 2816
#define NXg   128
#define NYg   128
#define NZg   16
#define NPTS  (NXg * NYg * NZg)  // 262144 points per batch
#define TPB   256
#define NCH8  (C_ / 8)           // 10 channel chunks of 8 fp16 channels (16 B)

// (B, H*W, C) channel-last fp16 copy of the feature map. 2*2816*80*2 B = 900 KB.
__device__ __half g_imgH[2 * HW_ * C_];

// ---------------------------------------------------------------------------
// Pass 1: (B, C, HW) f32 -> (B, HW, C) fp16 tiled transpose (L2-resident)
// ---------------------------------------------------------------------------
__global__ void fvt_transpose(const float* __restrict__ img)
{
    __shared__ float tile[32][33];
    const int b   = blockIdx.z;
    const int hw0 = blockIdx.x * 32;
    const int c0  = blockIdx.y * 32;
    const int tx  = threadIdx.x;      // 0..31
    const int ty  = threadIdx.y;      // 0..7

    #pragma unroll
    for (int i = 0; i < 4; i++) {
        const int c  = c0 + ty + i * 8;
        const int hw = hw0 + tx;
        if (c < C_ && hw < HW_)
            tile[ty + i * 8][tx] = img[((size_t)b * C_ + c) * HW_ + hw];
    }
    __syncthreads();
    #pragma unroll
    for (int i = 0; i < 4; i++) {
        const int hw = hw0 + ty + i * 8;
        const int c  = c0 + tx;
        if (hw < HW_ && c < C_)
            g_imgH[((size_t)b * HW_ + hw) * C_ + c] =
                __float2half_rn(tile[tx][ty + i * 8]);
    }
}

// ---------------------------------------------------------------------------
// Pass 2: thread-per-point. fp16 channel-last gathers (8 ch per LDG.128),
// f32 interpolation, streamed coalesced stores.
// ---------------------------------------------------------------------------
__global__ __launch_bounds__(TPB, 5) void fvt_kernel(
    const float* __restrict__ intrin,  // (B, 1, 4, 4)
    const float* __restrict__ extrin,  // (B, 1, 4, 4)
    const float* __restrict__ bda,     // (B, 4, 4)
    float* __restrict__ out)           // (B, C, NX, NY, NZ)
{
    __shared__ float s_bda[16];
    __shared__ float s_proj[12];

    const int b = blockIdx.y;

    if (threadIdx.x < 16) s_bda[threadIdx.x] = bda[b * 16 + threadIdx.x];
    if (threadIdx.x < 12) {
        // proj[i][j] = sum_k (intrin[i][k] * scale_i) * extrin[k][j]
        const int i = threadIdx.x >> 2;
        const int j = threadIdx.x & 3;
        const float sc = (i < 2) ? 0.125f : 1.0f;
        const float* IN = intrin + b * 16;
        const float* EX = extrin + b * 16;
        float acc = 0.0f;
        #pragma unroll
        for (int k = 0; k < 3; k++)
            acc += (IN[i * 4 + k] * sc) * EX[k * 4 + j];
        s_proj[threadIdx.x] = acc;
    }
    __syncthreads();

    const int n  = blockIdx.x * TPB + threadIdx.x;
    const int iz = n & (NZg - 1);
    const int t  = n >> 4;
    const int iy = t & (NYg - 1);
    const int ix = t >> 7;

    // match jnp: bound[0] + arange*step  (mul then add, no FMA contraction)
    const float px = __fadd_rn(__fmul_rn((float)ix, 0.8f), -51.2f);
    const float py = __fadd_rn(__fmul_rn((float)iy, 0.8f), -51.2f);
    const float pz = __fadd_rn(__fmul_rn((float)iz, 0.5f), -5.0f);

    // q = bda @ [px,py,pz,1]
    const float q0 = s_bda[ 0]*px + s_bda[ 1]*py + s_bda[ 2]*pz + s_bda[ 3];
    const float q1 = s_bda[ 4]*px + s_bda[ 5]*py + s_bda[ 6]*pz + s_bda[ 7];
    const float q2 = s_bda[ 8]*px + s_bda[ 9]*py + s_bda[10]*pz + s_bda[11];
    const float q3 = s_bda[12]*px + s_bda[13]*py + s_bda[14]*pz + s_bda[15];

    // pix = proj(3x4) @ q
    const float p0 = s_proj[0]*q0 + s_proj[1]*q1 + s_proj[ 2]*q2 + s_proj[ 3]*q3;
    const float p1 = s_proj[4]*q0 + s_proj[5]*q1 + s_proj[ 6]*q2 + s_proj[ 7]*q3;
    const float p2 = s_proj[8]*q0 + s_proj[9]*q1 + s_proj[10]*q2 + s_proj[11]*q3;

    const float u = __fdiv_rn(p0, p2);
    const float v = __fdiv_rn(p1, p2);

    // un = u/W*2-1 ; x = (un+1)*0.5*(W-1)   (replicate reference op order)
    const float un = __fadd_rn(__fmul_rn(__fdiv_rn(u, 88.0f), 2.0f), -1.0f);
    const float vn = __fadd_rn(__fmul_rn(__fdiv_rn(v, 32.0f), 2.0f), -1.0f);
    float x = __fmul_rn(__fmul_rn(__fadd_rn(un, 1.0f), 0.5f), 87.0f);
    float y = __fmul_rn(__fmul_rn(__fadd_rn(vn, 1.0f), 0.5f), 31.0f);

    // finite check via exponent bits (robust under any fast-math setting)
    const unsigned exb = __float_as_uint(x) & 0x7f800000u;
    const unsigned eyb = __float_as_uint(y) & 0x7f800000u;
    if (exb == 0x7f800000u || eyb == 0x7f800000u) { x = -10.0f; y = -10.0f; }

    const float x0f = floorf(x), y0f = floorf(y);
    const float x1f = x0f + 1.0f, y1f = y0f + 1.0f;
    const float wx1 = x - x0f, wx0 = 1.0f - wx1;
    const float wy1 = y - y0f, wy0 = 1.0f - wy1;

    const bool vx0 = (x0f >= 0.0f) && (x0f < 88.0f);
    const bool vx1 = (x1f >= 0.0f) && (x1f < 88.0f);
    const bool vy0 = (y0f >= 0.0f) && (y0f < 32.0f);
    const bool vy1 = (y1f >= 0.0f) && (y1f < 32.0f);

    const int ix0 = (int)fminf(fmaxf(x0f, 0.0f), 87.0f);
    const int ix1 = (int)fminf(fmaxf(x1f, 0.0f), 87.0f);
    const int iy0 = (int)fminf(fmaxf(y0f, 0.0f), 31.0f);
    const int iy1 = (int)fminf(fmaxf(y1f, 0.0f), 31.0f);

    const float w00 = (vx0 && vy0) ? wx0 * wy0 : 0.0f;
    const float w10 = (vx1 && vy0) ? wx1 * wy0 : 0.0f;
    const float w01 = (vx0 && vy1) ? wx0 * wy1 : 0.0f;
    const float w11 = (vx1 && vy1) ? wx1 * wy1 : 0.0f;

    const bool any = (vx0 || vx1) && (vy0 || vy1);

    float* ob = out + (size_t)b * C_ * NPTS + n;

    if (!any) {
        #pragma unroll
        for (int c = 0; c < C_; c++)
            __stcs(ob + (size_t)c * NPTS, 0.0f);
        return;
    }

    const __half* rowbase = g_imgH + (size_t)b * HW_ * C_;
    const float4* pc00 = (const float4*)(rowbase + (size_t)(iy0 * W_ + ix0) * C_);
    const float4* pc10 = (const float4*)(rowbase + (size_t)(iy0 * W_ + ix1) * C_);
    const float4* pc01 = (const float4*)(rowbase + (size_t)(iy1 * W_ + ix0) * C_);
    const float4* pc11 = (const float4*)(rowbase + (size_t)(iy1 * W_ + ix1) * C_);

    for (int ch = 0; ch < NCH8; ch++) {
        // front-batch the 4 corner loads (8 fp16 channels each, MLP=4)
        float4 ra = __ldg(pc00 + ch);
        float4 rb = __ldg(pc10 + ch);
        float4 rc = __ldg(pc01 + ch);
        float4 rd = __ldg(pc11 + ch);
        const __half2* ha = (const __half2*)&ra;
        const __half2* hb = (const __half2*)&rb;
        const __half2* hc = (const __half2*)&rc;
        const __half2* hd = (const __half2*)&rd;

        float* o = ob + (size_t)(ch * 8) * NPTS;
        #pragma unroll
        for (int k = 0; k < 4; k++) {
            const float2 fa = __half22float2(ha[k]);
            const float2 fb = __half22float2(hb[k]);
            const float2 fc = __half22float2(hc[k]);
            const float2 fd = __half22float2(hd[k]);
            const float r0 = w00*fa.x + w10*fb.x + w01*fc.x + w11*fd.x;
            const float r1 = w00*fa.y + w10*fb.y + w01*fc.y + w11*fd.y;
            __stcs(o + (size_t)(2 * k)     * NPTS, r0);
            __stcs(o + (size_t)(2 * k + 1) * NPTS, r1);
        }
    }
}

extern "C" void kernel_launch(void* const* d_in, const int* in_sizes, int n_in,
                              void* d_out, int out_size)
{
    (void)in_sizes; (void)n_in; (void)out_size;
    const float* img    = (const float*)d_in[0];
    const float* intrin = (const float*)d_in[1];
    const float* extrin = (const float*)d_in[2];
    const float* bda    = (const float*)d_in[3];
    float* out          = (float*)d_out;

    dim3 tgrid((HW_ + 31) / 32, (C_ + 31) / 32, 2);
    fvt_transpose<<<tgrid, dim3(32, 8)>>>(img);

    dim3 grid(NPTS / TPB, 2);   // 1024 blocks/batch, B=2
    fvt_kernel<<<grid, TPB>>>(intrin, extrin, bda, out);
}